// round 6
// baseline (speedup 1.0000x reference)
#include <cuda_runtime.h>
#include <cstdint>

// Problem constants (fixed by the reference)
#define BB   32
#define CC   128
#define HH   128
#define WW   128
#define OH   64
#define OW   64
// output plane stride (vals / pos_h / pos_w planes), in elements
#define PLANE (CC * OH * OW)   // 524288

// logical tiles: one warp-tile = (bc, output-row-pair); 4096 * 32 = 131072 warp-tiles
#define NTILES (BB * CC * (OH / 2))   // 131072

__device__ __forceinline__ void win2x2(float a, float b, float c, float d,
                                       int row0, int col0,
                                       float& val, float& ph, float& pw) {
    // first-max argmax over order [a, b, c, d] == flat idx kh*2+kw
    float best = a; int idx = 0;
    if (b > best) { best = b; idx = 1; }
    if (c > best) { best = c; idx = 2; }
    if (d > best) { best = d; idx = 3; }
    int row = row0 + (idx >> 1);
    int col = col0 + (idx & 1);
    val = best;
    ph = (float)row * (1.0f / (float)HH);
    pw = (float)col * (1.0f / (float)WW);
}

__global__ void __launch_bounds__(256)
pap_pool_kernel(const float* __restrict__ x, float* __restrict__ out) {
    // Persistent grid-stride over warp-tiles. Inner mapping identical to R4:
    // one warp-tile = one bc, two output rows (4 input rows); lane l covers
    // input cols [4l, 4l+4). Every LDG.128 is 512B warp-contiguous; every
    // STG.64 is 256B warp-contiguous.
    const unsigned lane    = threadIdx.x & 31u;
    const unsigned warp_in = threadIdx.x >> 5;                 // 0..7
    const unsigned nwarps  = (gridDim.x * blockDim.x) >> 5;    // total warps in grid
    unsigned wt = blockIdx.x * (blockDim.x >> 5) + warp_in;    // first warp-tile

    for (; wt < NTILES; wt += nwarps) {
        unsigned ohp = wt & 31u;    // output-row pair index, 0..31
        unsigned bc  = wt >> 5;     // b*C + c, 0..4095

        // input rows 4*ohp .. 4*ohp+3 of channel bc
        const float4* p = reinterpret_cast<const float4*>(
            x + bc * (HH * WW) + (4u * ohp) * WW) + lane;

        // front-batch 4 perfectly-coalesced loads (512B/instr, MLP=4)
        float4 r0 = p[0];
        float4 r1 = p[32];
        float4 r2 = p[64];
        float4 r3 = p[96];

        int row0 = 4 * (int)ohp;
        int col0 = 4 * (int)lane;

        float va0, pha0, pwa0, va1, pha1, pwa1;
        float vb0, phb0, pwb0, vb1, phb1, pwb1;
        win2x2(r0.x, r0.y, r1.x, r1.y, row0,     col0,     va0, pha0, pwa0);
        win2x2(r0.z, r0.w, r1.z, r1.w, row0,     col0 + 2, va1, pha1, pwa1);
        win2x2(r2.x, r2.y, r3.x, r3.y, row0 + 2, col0,     vb0, phb0, pwb0);
        win2x2(r2.z, r2.w, r3.z, r3.w, row0 + 2, col0 + 2, vb1, phb1, pwb1);

        // output: [B, 3C, OH, OW]; b = bc/128, c = bc%128
        unsigned b = bc >> 7;
        unsigned c = bc & 127u;
        unsigned oh0 = 2u * ohp;
        float* o = out + ((b * 3u * CC + c) * OH + oh0) * OW + 2u * lane;

        *reinterpret_cast<float2*>(o)                  = make_float2(va0, va1);
        *reinterpret_cast<float2*>(o + OW)             = make_float2(vb0, vb1);
        *reinterpret_cast<float2*>(o + PLANE)          = make_float2(pha0, pha1);
        *reinterpret_cast<float2*>(o + PLANE + OW)     = make_float2(phb0, phb1);
        *reinterpret_cast<float2*>(o + 2 * PLANE)      = make_float2(pwa0, pwa1);
        *reinterpret_cast<float2*>(o + 2 * PLANE + OW) = make_float2(pwb0, pwb1);
    }
}

extern "C" void kernel_launch(void* const* d_in, const int* in_sizes, int n_in,
                              void* d_out, int out_size) {
    const float* x = (const float*)d_in[0];
    float* out = (float*)d_out;
    // Persistent: 148 SMs x 8 CTAs/SM = 1184 CTAs of 256 threads.
    // Each of the 9472 warps iterates over ~13.8 of the 131072 warp-tiles.
    pap_pool_kernel<<<1184, 256>>>(x, out);
}

// round 7
// speedup vs baseline: 1.1396x; 1.1396x over previous
#include <cuda_runtime.h>
#include <cstdint>

// Problem constants (fixed by the reference)
#define BB   32
#define CC   128
#define HH   128
#define WW   128
#define OH   64
#define OW   64
// output plane stride (vals / pos_h / pos_w planes), in elements
#define PLANE (CC * OH * OW)   // 524288

__device__ __forceinline__ void win2x2(float a, float b, float c, float d,
                                       int row0, int col0,
                                       float& val, float& ph, float& pw) {
    // first-max argmax over order [a, b, c, d] == flat idx kh*2+kw
    float best = a; int idx = 0;
    if (b > best) { best = b; idx = 1; }
    if (c > best) { best = c; idx = 2; }
    if (d > best) { best = d; idx = 3; }
    int row = row0 + (idx >> 1);
    int col = col0 + (idx & 1);
    val = best;
    ph = (float)row * (1.0f / (float)HH);
    pw = (float)col * (1.0f / (float)WW);
}

__global__ void __launch_bounds__(512)
pap_pool_kernel(const float* __restrict__ x, float* __restrict__ out) {
    // One WARP owns: one bc, two output rows (oh0, oh0+1) = 4 input rows.
    // Lane l loads float4 at column 4*l of each of the 4 input rows:
    // every LDG.128 is 32 lanes x 16B = 512B fully contiguous.
    // total warps = B*C*(OH/2) = 4096*32 = 131072 -> 4,194,304 threads.
    unsigned tid  = blockIdx.x * blockDim.x + threadIdx.x;
    unsigned lane = tid & 31u;
    unsigned w    = tid >> 5;

    unsigned ohp = w & 31u;    // output-row pair index, 0..31
    unsigned bc  = w >> 5;     // b*C + c, 0..4095

    // input rows 4*ohp .. 4*ohp+3 of channel bc
    const float4* p = reinterpret_cast<const float4*>(
        x + bc * (HH * WW) + (4u * ohp) * WW) + lane;

    // front-batch 4 perfectly-coalesced loads (512B/instr, MLP=4)
    float4 r0 = p[0];
    float4 r1 = p[32];
    float4 r2 = p[64];
    float4 r3 = p[96];

    int row0 = 4 * (int)ohp;
    int col0 = 4 * (int)lane;

    // rows (r0,r1) -> output row oh0 = 2*ohp; rows (r2,r3) -> oh0+1
    float va0, pha0, pwa0, va1, pha1, pwa1;
    float vb0, phb0, pwb0, vb1, phb1, pwb1;
    win2x2(r0.x, r0.y, r1.x, r1.y, row0,     col0,     va0, pha0, pwa0);
    win2x2(r0.z, r0.w, r1.z, r1.w, row0,     col0 + 2, va1, pha1, pwa1);
    win2x2(r2.x, r2.y, r3.x, r3.y, row0 + 2, col0,     vb0, phb0, pwb0);
    win2x2(r2.z, r2.w, r3.z, r3.w, row0 + 2, col0 + 2, vb1, phb1, pwb1);

    // output: [B, 3C, OH, OW]; b = bc/128, c = bc%128
    unsigned b = bc >> 7;
    unsigned c = bc & 127u;
    unsigned oh0 = 2u * ohp;
    float* o = out + ((b * 3u * CC + c) * OH + oh0) * OW + 2u * lane;

    // 6 STG.64, each 32 lanes x 8B = 256B contiguous
    *reinterpret_cast<float2*>(o)                  = make_float2(va0, va1);
    *reinterpret_cast<float2*>(o + OW)             = make_float2(vb0, vb1);
    *reinterpret_cast<float2*>(o + PLANE)          = make_float2(pha0, pha1);
    *reinterpret_cast<float2*>(o + PLANE + OW)     = make_float2(phb0, phb1);
    *reinterpret_cast<float2*>(o + 2 * PLANE)      = make_float2(pwa0, pwa1);
    *reinterpret_cast<float2*>(o + 2 * PLANE + OW) = make_float2(pwb0, pwb1);
}

extern "C" void kernel_launch(void* const* d_in, const int* in_sizes, int n_in,
                              void* d_out, int out_size) {
    const float* x = (const float*)d_in[0];
    float* out = (float*)d_out;
    // 4,194,304 threads total; block = 512 (R4 pattern, half the CTA count)
    const unsigned nthreads = BB * CC * (OH / 2) * 32;
    const unsigned block = 512;
    pap_pool_kernel<<<nthreads / block, block>>>(x, out);
}